// round 2
// baseline (speedup 1.0000x reference)
#include <cuda_runtime.h>

// Problem constants (fixed by the reference)
#define BB    256        // batch
#define TT    16384      // series length
#define WIN   5
#define HID   5
#define NN    (TT - WIN) // 16379 positions

#define GROUPS 32            // b-groups per block (t>>3)
#define LANES  8             // n-lanes per block  (t&7)
#define BPG    (BB / GROUPS) // 8 b per thread
#define NPT    8             // n per thread (4 packed pairs)
#define NPB    (LANES * NPT) // 64 n per block
#define NBLK   ((NN + NPB - 1) / NPB) // 256 blocks

typedef unsigned long long ull;

__device__ __forceinline__ ull pack2(float lo, float hi) {
    ull r;
    asm("mov.b64 %0, {%1, %2};" : "=l"(r) : "f"(lo), "f"(hi));
    return r;
}
__device__ __forceinline__ void unpack2(float& lo, float& hi, ull v) {
    asm("mov.b64 {%0, %1}, %2;" : "=f"(lo), "=f"(hi) : "l"(v));
}
// d = a*b + c  (packed 2x fp32)
__device__ __forceinline__ void fma2(ull& d, ull a, ull b, ull c) {
    asm("fma.rn.f32x2 %0, %1, %2, %3;" : "=l"(d) : "l"(a), "l"(b), "l"(c));
}

__global__ void __launch_bounds__(256, 2)
llsa_main_kernel(const float* __restrict__ series,
                 const float* __restrict__ weight,
                 const float* __restrict__ bias,
                 float* __restrict__ out)
{
    __shared__ float sred[NPB * 33];   // [64 n][32 g], pad 33 vs bank conflicts

    const int t  = threadIdx.x;
    const int g  = t >> 3;             // b-group 0..31
    const int l  = t & 7;              // n-lane  0..7
    const int n0 = blockIdx.x * NPB;
    const int base = n0 + l * NPT;     // first n for this thread

    // Pack weights/bias into broadcast f32x2 registers.
    ull W2[HID][WIN], b2[HID];
#pragma unroll
    for (int h = 0; h < HID; h++) {
        float bh = __ldg(&bias[h]);
        b2[h] = pack2(bh, bh);
#pragma unroll
        for (int w = 0; w < WIN; w++) {
            float wv = __ldg(&weight[h * WIN + w]);
            W2[h][w] = pack2(wv, wv);
        }
    }
    const ull neg2 = pack2(-1.0f, -1.0f);

    ull acc2[NPT / 2] = {0ull, 0ull, 0ull, 0ull};  // bit pattern 0 == (0.0f,0.0f)

    const bool fast = (base + 16 <= TT);
    const float* __restrict__ row0 = series + (size_t)(g * BPG) * TT + base;

#pragma unroll 2
    for (int bb = 0; bb < BPG; bb++) {
        const float* __restrict__ row = row0 + (size_t)bb * TT;

        float x[16];
        if (fast) {
            const float4* p4 = reinterpret_cast<const float4*>(row);
            float4 v0 = __ldg(&p4[0]);
            float4 v1 = __ldg(&p4[1]);
            float4 v2 = __ldg(&p4[2]);
            float4 v3 = __ldg(&p4[3]);
            x[0]=v0.x;  x[1]=v0.y;  x[2]=v0.z;  x[3]=v0.w;
            x[4]=v1.x;  x[5]=v1.y;  x[6]=v1.z;  x[7]=v1.w;
            x[8]=v2.x;  x[9]=v2.y;  x[10]=v2.z; x[11]=v2.w;
            x[12]=v3.x; x[13]=v3.y; x[14]=v3.z; x[15]=v3.w;
        } else {
            // Only the last block's l==7 threads take this path.
#pragma unroll
            for (int j = 0; j < 16; j++)
                x[j] = (base + j < TT) ? __ldg(&row[j]) : 0.0f;
        }

        // Adjacent pairs p[j] = (x[j], x[j+1]) cover every packed operand.
        ull p[12];
#pragma unroll
        for (int j = 0; j < 12; j++)
            p[j] = pack2(x[j], x[j + 1]);

#pragma unroll
        for (int pi = 0; pi < NPT / 2; pi++) {
            const int i = 2 * pi;          // lo lane n = base+i, hi lane n = base+i+1
#pragma unroll
            for (int h = 0; h < HID; h++) {
                ull th = b2[h];
#pragma unroll
                for (int w = 0; w < WIN; w++)
                    fma2(th, W2[h][w], p[i + w], th);
                ull d;
                fma2(d, p[i + 1 + h], neg2, th);   // th - target
                fma2(acc2[pi], d, d, acc2[pi]);
            }
        }
    }

    // Scatter per-(n,g) partials to smem.
#pragma unroll
    for (int pi = 0; pi < NPT / 2; pi++) {
        float alo, ahi;
        unpack2(alo, ahi, acc2[pi]);
        sred[(l * NPT + 2 * pi    ) * 33 + g] = alo;
        sred[(l * NPT + 2 * pi + 1) * 33 + g] = ahi;
    }
    __syncthreads();

    // Reduce 32 groups per n: 4 threads per n, 8 sequential + 2 shfl.
    const int n = t >> 2;      // 0..63
    const int q = t & 3;       // quarter
    float s = 0.0f;
#pragma unroll
    for (int j = 0; j < 8; j++)
        s += sred[n * 33 + q * 8 + j];
    s += __shfl_xor_sync(0xffffffffu, s, 1);
    s += __shfl_xor_sync(0xffffffffu, s, 2);

    if (q == 0) {
        const int nn = n0 + n;
        if (nn < NN)
            out[nn] = s * (1.0f / (float)(BB * HID));
    }
}

__global__ void __launch_bounds__(256)
llsa_diff_kernel(float* __restrict__ out, const float* __restrict__ thr_p)
{
    const int n = blockIdx.x * blockDim.x + threadIdx.x;
    if (n >= NN - 1) return;
    const float l0 = out[n];
    const float l1 = out[n + 1];
    const float d = fabsf(l1 - l0);
    out[NN + n] = d;
    out[2 * NN - 1 + n] = (d > *thr_p) ? 1.0f : 0.0f;
}

extern "C" void kernel_launch(void* const* d_in, const int* in_sizes, int n_in,
                              void* d_out, int out_size)
{
    const float* series = (const float*)d_in[0];
    const float* weight = (const float*)d_in[1];
    const float* bias   = (const float*)d_in[2];
    const float* thr    = (const float*)d_in[3];
    float* out = (float*)d_out;

    llsa_main_kernel<<<NBLK, 256>>>(series, weight, bias, out);
    llsa_diff_kernel<<<(NN - 1 + 255) / 256, 256>>>(out, thr);
}